// round 10
// baseline (speedup 1.0000x reference)
#include <cuda_runtime.h>
#include <cstdint>
#include <cstddef>
#include <math_constants.h>

#define NN 100000
#define EE 1600000
#define FIN 64
#define RR 8
#define GG 256
#define HH 4
#define CC 32
#define HC 128

// ---------------- scratch (device globals; no allocation allowed) -------------
__device__ float d_h[NN * HC];          // GAT pre-activation features
__device__ float d_asrc[NN * HH];
__device__ float d_adst[NN * HH];
__device__ int   d_deg[NN];
__device__ int   d_rowstart[NN + 1];
__device__ int   d_cursor[NN];
__device__ int   d_bsums[256];
__device__ int   d_epk[EE];             // per-(dst-sorted) edge: src | (et<<24)
__device__ float d_gat1[NN * HC];
__device__ float d_gat2[NN * 16];
__device__ float d_gmax[GG * 16];
__device__ float d_xw1[RR * NN * 32];
__device__ float d_z[NN * 32];
__device__ float d_xw2[RR * NN * 16];
__device__ float d_z2r[NN * 16];
__device__ float d_gmean[GG * 16];

// ---------------- utility ----------------
__device__ __forceinline__ float lrelu(float v, float s) { return v > 0.f ? v : s * v; }

__device__ __forceinline__ unsigned long long pk2(float lo, float hi) {
    unsigned long long r;
    asm("mov.b64 %0, {%1, %2};" : "=l"(r) : "f"(lo), "f"(hi));
    return r;
}
__device__ __forceinline__ void upk2(unsigned long long v, float& lo, float& hi) {
    asm("mov.b64 {%0, %1}, %2;" : "=f"(lo), "=f"(hi) : "l"(v));
}
__device__ __forceinline__ unsigned long long ffma2(unsigned long long a, unsigned long long b,
                                                    unsigned long long c) {
    unsigned long long d;
    asm("fma.rn.f32x2 %0, %1, %2, %3;" : "=l"(d) : "l"(a), "l"(b), "l"(c));
    return d;
}

// ---------------- zero init ----------------
__global__ void zero_kernel() {
    int i = blockIdx.x * blockDim.x + threadIdx.x;
    if (i < NN) { d_deg[i] = 0; d_cursor[i] = 0; }
    if (i < GG * 16) d_gmean[i] = 0.f;
}

// ---------------- packed-f32 tiled SGEMM  Y[r,c] = sum_k X[r,k] W[k,c] --------
// f32x2 row-pair accumulation. 128-bit smem paths:
//   sX stride BR+4 (16B-mult) -> x pairs read as ulonglong2 (LDS.128)
//   W read as float4 (LDS.128), packed {w,w} on the fly
//   fill: float4 gmem reads, consecutive-r STS (conflict-free)
// grid.z selects relation matrix (z < nRel -> Wrel/Yrel, else Wroot/Yroot).
// ACT: 0 none, 1 leaky_relu(0.01), 2 relu. FATT: fused GAT attention epilogue.
template<int K, int KC, int NCT, int BR, int TR, int TC, int TX, int TY,
         int ACT, bool BIAS, bool FATT>
__global__ __launch_bounds__(TX * TY) void gemm2_k(
    const float* __restrict__ X,
    const float* __restrict__ Wrel, const float* __restrict__ Wroot,
    float* __restrict__ Yrel, size_t yStride, float* __restrict__ Yroot,
    int nRel, const float* __restrict__ bias,
    const float* __restrict__ attS, const float* __restrict__ attD,
    int nrows, int ncolsTotal)
{
    constexpr int NT = TX * TY;
    static_assert(TY * TR == BR, "row tiling");
    static_assert(TX * TC == NCT, "col tiling");
    static_assert(TR % 4 == 0 && TC % 4 == 0, "tiles mult of 4 for 128-bit LDS");
    static_assert((BR + 4) % 4 == 0 && K % 4 == 0 && KC % 4 == 0, "align");
    static_assert(!FATT || (TC == 8 && TX == 8 && NCT == 64), "FATT layout");

    __shared__ __align__(16) float sW[K * NCT];
    __shared__ __align__(16) float sX[KC][BR + 4];

    int z = blockIdx.z;
    const float* W = (z < nRel) ? (Wrel + (size_t)z * K * ncolsTotal) : Wroot;
    float*       Y = (z < nRel) ? (Yrel + (size_t)z * yStride)        : Yroot;

    int tid = threadIdx.x;
    int tx = tid % TX, ty = tid / TX;
    int r0 = blockIdx.x * BR;
    int c0 = blockIdx.y * NCT;

    for (int i = tid; i < K * NCT; i += NT) {
        int k = i / NCT, c = i % NCT;
        sW[i] = W[(size_t)k * ncolsTotal + c0 + c];
    }

    unsigned long long acc[TR / 2][TC];
#pragma unroll
    for (int p = 0; p < TR / 2; p++)
#pragma unroll
        for (int j = 0; j < TC; j++) acc[p][j] = 0ull;

    for (int k0 = 0; k0 < K; k0 += KC) {
        __syncthreads();
        // fill: thread reads float4 of X (4 k's, one row), stores to 4 sX rows
        // consecutive tids -> consecutive r => conflict-free STS
        constexpr int NF4 = BR * KC / 4;
        for (int f = tid; f < NF4; f += NT) {
            int r = f % BR;
            int k4 = f / BR;
            float4 v = make_float4(0.f, 0.f, 0.f, 0.f);
            if (r0 + r < nrows)
                v = *(const float4*)&X[(size_t)(r0 + r) * K + k0 + 4 * k4];
            sX[4 * k4 + 0][r] = v.x;
            sX[4 * k4 + 1][r] = v.y;
            sX[4 * k4 + 2][r] = v.z;
            sX[4 * k4 + 3][r] = v.w;
        }
        __syncthreads();
#pragma unroll 8
        for (int kk = 0; kk < KC; kk++) {
            unsigned long long xp[TR / 2];
            const ulonglong2* xr = (const ulonglong2*)&sX[kk][ty * TR];
#pragma unroll
            for (int q = 0; q < TR / 4; q++) {
                ulonglong2 t = xr[q];
                xp[2 * q]     = t.x;
                xp[2 * q + 1] = t.y;
            }
            unsigned long long wp[TC];
#pragma unroll
            for (int j4 = 0; j4 < TC / 4; j4++) {
                float4 wv = *(const float4*)&sW[(k0 + kk) * NCT + tx * TC + 4 * j4];
                wp[4 * j4 + 0] = pk2(wv.x, wv.x);
                wp[4 * j4 + 1] = pk2(wv.y, wv.y);
                wp[4 * j4 + 2] = pk2(wv.z, wv.z);
                wp[4 * j4 + 3] = pk2(wv.w, wv.w);
            }
#pragma unroll
            for (int p = 0; p < TR / 2; p++)
#pragma unroll
                for (int j = 0; j < TC; j++)
                    acc[p][j] = ffma2(xp[p], wp[j], acc[p][j]);
        }
    }

    // attention vectors (FATT only)
    float attSr[TC], attDr[TC];
    int head = 0;
    if (FATT) {
        head = blockIdx.y * 2 + (tx >> 2);
        int cb = (tx & 3) * TC;
#pragma unroll
        for (int j = 0; j < TC; j++) {
            attSr[j] = attS[head * 32 + cb + j];
            attDr[j] = attD[head * 32 + cb + j];
        }
    }

#pragma unroll
    for (int p = 0; p < TR / 2; p++) {
        float v2[2][TC];
#pragma unroll
        for (int j = 0; j < TC; j++) upk2(acc[p][j], v2[0][j], v2[1][j]);
#pragma unroll
        for (int half = 0; half < 2; half++) {
            int r = r0 + ty * TR + 2 * p + half;
            float* v = v2[half];
            if (r < nrows) {
                float o[TC];
#pragma unroll
                for (int j = 0; j < TC; j++) {
                    float t = v[j];
                    if (BIAS) t += bias[c0 + tx * TC + j];
                    if (ACT == 1) t = lrelu(t, 0.01f);
                    if (ACT == 2) t = t > 0.f ? t : 0.f;
                    o[j] = t;
                }
#pragma unroll
                for (int j4 = 0; j4 < TC; j4 += 4) {
                    float4 st = make_float4(o[j4], o[j4 + 1], o[j4 + 2], o[j4 + 3]);
                    *(float4*)&Y[(size_t)r * ncolsTotal + c0 + tx * TC + j4] = st;
                }
            }
            if (FATT) {
                float ss = 0.f, sd = 0.f;
#pragma unroll
                for (int j = 0; j < TC; j++) { ss = fmaf(v[j], attSr[j], ss); sd = fmaf(v[j], attDr[j], sd); }
                ss += __shfl_xor_sync(0xffffffffu, ss, 1);
                ss += __shfl_xor_sync(0xffffffffu, ss, 2);
                sd += __shfl_xor_sync(0xffffffffu, sd, 1);
                sd += __shfl_xor_sync(0xffffffffu, sd, 2);
                if ((tx & 3) == 0 && r < nrows) {
                    d_asrc[r * 4 + head] = ss;
                    d_adst[r * 4 + head] = sd;
                }
            }
        }
    }
}

// ---------------- CSR build ----------------
__global__ void deg_kernel(const int* __restrict__ ei) {
    int i = blockIdx.x * blockDim.x + threadIdx.x;
    if (i < EE) atomicAdd(&d_deg[ei[EE + i]], 1);
}

__global__ void scan_block() {
    __shared__ int s[1024];
    int i = blockIdx.x * 1024 + threadIdx.x;
    int v = (i < NN) ? d_deg[i] : 0;
    s[threadIdx.x] = v;
    __syncthreads();
    for (int off = 1; off < 1024; off <<= 1) {
        int t = (threadIdx.x >= off) ? s[threadIdx.x - off] : 0;
        __syncthreads();
        s[threadIdx.x] += t;
        __syncthreads();
    }
    if (i < NN) d_rowstart[i] = s[threadIdx.x] - v;   // exclusive
    if (threadIdx.x == 1023) d_bsums[blockIdx.x] = s[1023];
}

// fused: each block computes the prefix of raw block sums itself, then adds
__global__ void scan_add() {
    __shared__ int base;
    int b = blockIdx.x;
    int tid = threadIdx.x;
    if (tid < 32) {
        int acc = 0;
        for (int i = tid; i < b; i += 32) acc += d_bsums[i];
#pragma unroll
        for (int o = 16; o >= 1; o >>= 1) acc += __shfl_xor_sync(0xffffffffu, acc, o);
        if (tid == 0) base = acc;
    }
    __syncthreads();
    int i = b * 1024 + tid;
    if (i < NN) d_rowstart[i] += base;
    if (i == 0) d_rowstart[NN] = EE;
}

__global__ void scatter_kernel(const int* __restrict__ ei, const int* __restrict__ et) {
    int i = blockIdx.x * blockDim.x + threadIdx.x;
    if (i >= EE) return;
    int d = ei[EE + i];
    int pos = d_rowstart[d] + atomicAdd(&d_cursor[d], 1);
    d_epk[pos] = ei[i] | (et[i] << 24);
}

// ---------------- GAT aggregation (warp per dst node, single-pass softmax) ----
__global__ void gat_agg(const float* __restrict__ bias) {
    int w = threadIdx.x >> 5;
    int n = blockIdx.x * 8 + w;
    if (n >= NN) return;
    int lane = threadIdx.x & 31;
    int s0 = d_rowstart[n], s1 = d_rowstart[n + 1];
    int head = lane >> 3;

    float4 adAll = ((const float4*)d_adst)[n];

    __shared__ int   ssrc[8][32];
    __shared__ float sp[8][4][32];
    const float4* asrc4 = (const float4*)d_asrc;
    const float4* h4    = (const float4*)d_h;

    float4 acc = make_float4(0.f, 0.f, 0.f, 0.f);
    float ps = 0.f;

    for (int base = s0; base < s1; base += 32) {
        int cnt = min(32, s1 - base);
        if (lane < cnt) {
            int src = d_epk[base + lane] & 0xFFFFFF;
            ssrc[w][lane] = src;
            float4 as = asrc4[src];
            sp[w][0][lane] = __expf(lrelu(as.x + adAll.x, 0.2f));
            sp[w][1][lane] = __expf(lrelu(as.y + adAll.y, 0.2f));
            sp[w][2][lane] = __expf(lrelu(as.z + adAll.z, 0.2f));
            sp[w][3][lane] = __expf(lrelu(as.w + adAll.w, 0.2f));
        }
        __syncwarp();
#pragma unroll 4
        for (int j = 0; j < cnt; j++) {
            float p = sp[w][head][j];
            int src = ssrc[w][j];
            float4 hv = h4[(size_t)src * 32 + lane];
            acc.x = fmaf(p, hv.x, acc.x);
            acc.y = fmaf(p, hv.y, acc.y);
            acc.z = fmaf(p, hv.z, acc.z);
            acc.w = fmaf(p, hv.w, acc.w);
            ps += p;
        }
        __syncwarp();
    }

    float inv = (s1 > s0) ? (1.f / ps) : 0.f;
    float4 b4 = ((const float4*)bias)[lane];
    float4 o;
    o.x = lrelu(acc.x * inv + b4.x, 0.01f);
    o.y = lrelu(acc.y * inv + b4.y, 0.01f);
    o.z = lrelu(acc.z * inv + b4.z, 0.01f);
    o.w = lrelu(acc.w * inv + b4.w, 0.01f);
    ((float4*)d_gat1)[(size_t)n * 32 + lane] = o;
}

// ---------------- per-graph max pool of d_gat2 -> d_gmax ----------------
__global__ void gmax_kernel() {
    int g = blockIdx.x;
    int st = (g * NN + GG - 1) / GG;
    int en = ((g + 1) * NN + GG - 1) / GG;
    int tid = threadIdx.x;
    int col = tid % 16, part = tid / 16;            // 8 partitions
    float m = -CUDART_INF_F;
    for (int r = st + part; r < en; r += 8) m = fmaxf(m, d_gat2[(size_t)r * 16 + col]);
    __shared__ float sm[128];
    sm[tid] = m;
    __syncthreads();
    for (int o = 64; o >= 16; o >>= 1) {
        if (tid < o) sm[tid] = fmaxf(sm[tid], sm[tid + o]);
        __syncthreads();
    }
    if (tid < 16) d_gmax[g * 16 + tid] = sm[tid];
}

// ---------------- RGCN layer 1 aggregation (warp per node) ----------------
__global__ void rgcn1_agg(const float* __restrict__ rb) {
    int w = threadIdx.x >> 5;
    int n = blockIdx.x * 8 + w;
    if (n >= NN) return;
    int lane = threadIdx.x & 31;
    int s0 = d_rowstart[n], s1 = d_rowstart[n + 1];

    __shared__ int   scnt[8][8];
    __shared__ float sinv[8][8];
    __shared__ int   soff[8][32];
    __shared__ float sif[8][32];

    if (lane < 8) scnt[w][lane] = 0;
    __syncwarp();
    for (int e = s0 + lane; e < s1; e += 32) atomicAdd(&scnt[w][d_epk[e] >> 24], 1);
    __syncwarp();
    if (lane < 8) { int c = scnt[w][lane]; sinv[w][lane] = (c > 0) ? 1.f / (float)c : 0.f; }
    __syncwarp();

    float acc = 0.f;
    for (int base = s0; base < s1; base += 32) {
        int cnt = min(32, s1 - base);
        if (lane < cnt) {
            int v = d_epk[base + lane];
            int et = v >> 24, src = v & 0xFFFFFF;
            soff[w][lane] = (et * NN + src) * 32;
            sif[w][lane] = sinv[w][et];
        }
        __syncwarp();
#pragma unroll 4
        for (int j = 0; j < cnt; j++)
            acc = fmaf(__ldg(&d_xw1[soff[w][j] + lane]), sif[w][j], acc);
        __syncwarp();
    }
    float v = acc + d_z[(size_t)n * 32 + lane] + rb[lane];
    d_z[(size_t)n * 32 + lane] = v > 0.f ? v : 0.f;
}

// ---------------- RGCN layer 2 aggregation + graph-mean accumulation ----------------
__global__ void rgcn2_agg(const float* __restrict__ rb) {
    int w = threadIdx.x >> 5;
    int n = blockIdx.x * 8 + w;
    if (n >= NN) return;
    int lane = threadIdx.x & 31;
    int ch = lane & 15, par = lane >> 4;
    int s0 = d_rowstart[n], s1 = d_rowstart[n + 1];

    __shared__ int   scnt[8][8];
    __shared__ float sinv[8][8];
    __shared__ int   soff[8][32];
    __shared__ float sif[8][32];

    if (lane < 8) scnt[w][lane] = 0;
    __syncwarp();
    for (int e = s0 + lane; e < s1; e += 32) atomicAdd(&scnt[w][d_epk[e] >> 24], 1);
    __syncwarp();
    if (lane < 8) { int c = scnt[w][lane]; sinv[w][lane] = (c > 0) ? 1.f / (float)c : 0.f; }
    __syncwarp();

    float acc = 0.f;
    for (int base = s0; base < s1; base += 32) {
        int cnt = min(32, s1 - base);
        if (lane < cnt) {
            int v = d_epk[base + lane];
            int et = v >> 24, src = v & 0xFFFFFF;
            soff[w][lane] = (et * NN + src) * 16;
            sif[w][lane] = sinv[w][et];
        }
        __syncwarp();
#pragma unroll 4
        for (int j = par; j < cnt; j += 2)
            acc = fmaf(__ldg(&d_xw2[soff[w][j] + ch]), sif[w][j], acc);
        __syncwarp();
    }
    acc += __shfl_xor_sync(0xffffffffu, acc, 16);
    if (lane < 16) {
        float v = acc + d_z2r[(size_t)n * 16 + lane] + rb[lane];
        v = v > 0.f ? v : 0.f;
        int g = (n * GG) / NN;
        atomicAdd(&d_gmean[g * 16 + lane], v);
    }
}

// ---------------- final: [gmax | gmean] @ dense_w + dense_b ----------------
__global__ void final_kernel(const float* __restrict__ dw, const float* __restrict__ db,
                             float* __restrict__ out) {
    int g = blockIdx.x * 8 + (threadIdx.x >> 5);
    if (g >= GG) return;
    int lane = threadIdx.x & 31;
    int st = (g * NN + GG - 1) / GG;
    int en = ((g + 1) * NN + GG - 1) / GG;
    float npg = (float)(en - st);
    float v;
    if (lane < 16) v = d_gmax[g * 16 + lane] * dw[lane];
    else           v = (d_gmean[g * 16 + (lane - 16)] / npg) * dw[lane];
#pragma unroll
    for (int o = 16; o >= 1; o >>= 1) v += __shfl_xor_sync(0xffffffffu, v, o);
    if (lane == 0) out[g] = v + db[0];
}

// ---------------- host launcher (GAT gemm at slot 4 for ncu) ------------------
extern "C" void kernel_launch(void* const* d_in, const int* in_sizes, int n_in,
                              void* d_out, int out_size) {
    const float* x        = (const float*)d_in[0];
    const int*   ei       = (const int*)d_in[1];
    const int*   etyp     = (const int*)d_in[2];
    const float* gat_w    = (const float*)d_in[4];
    const float* att_src  = (const float*)d_in[5];
    const float* att_dst  = (const float*)d_in[6];
    const float* gat_bias = (const float*)d_in[7];
    const float* dense1_w = (const float*)d_in[8];
    const float* dense1_b = (const float*)d_in[9];
    const float* rw1      = (const float*)d_in[10];
    const float* root1    = (const float*)d_in[11];
    const float* rb1      = (const float*)d_in[12];
    const float* rw2      = (const float*)d_in[13];
    const float* root2    = (const float*)d_in[14];
    const float* rb2      = (const float*)d_in[15];
    const float* dense_w  = (const float*)d_in[16];
    const float* dense_b  = (const float*)d_in[17];
    float* out = (float*)d_out;

    float *p_h, *p_gat1, *p_gat2, *p_xw1, *p_z, *p_xw2, *p_z2r;
    cudaGetSymbolAddress((void**)&p_h, d_h);
    cudaGetSymbolAddress((void**)&p_gat1, d_gat1);
    cudaGetSymbolAddress((void**)&p_gat2, d_gat2);
    cudaGetSymbolAddress((void**)&p_xw1, d_xw1);
    cudaGetSymbolAddress((void**)&p_z, d_z);
    cudaGetSymbolAddress((void**)&p_xw2, d_xw2);
    cudaGetSymbolAddress((void**)&p_z2r, d_z2r);

    // 1-3
    zero_kernel<<<(NN + 255) / 256, 256>>>();
    deg_kernel<<<6250, 256>>>(ei);
    scan_block<<<98, 1024>>>();
    // 4: GAT feature GEMM (+ fused attention scalars) — profiled by ncu
    gemm2_k<64, 32, 64, 128, 8, 8, 8, 16, 0, false, true><<<dim3(782, 2, 1), 128>>>(
        x, nullptr, gat_w, nullptr, 0, p_h, 0, nullptr, att_src, att_dst, NN, HC);
    // 5-6: rest of CSR build
    scan_add<<<98, 1024>>>();
    scatter_kernel<<<6250, 256>>>(ei, etyp);

    // GAT branch
    gat_agg<<<12500, 256>>>(gat_bias);
    gemm2_k<128, 32, 16, 256, 8, 4, 4, 32, 1, true, false><<<dim3(391, 1, 1), 128>>>(
        p_gat1, nullptr, dense1_w, nullptr, 0, p_gat2, 0, dense1_b, nullptr, nullptr, NN, 16);
    gmax_kernel<<<GG, 128>>>();

    // RGCN branch
    gemm2_k<64, 32, 32, 128, 8, 4, 8, 16, 0, false, false><<<dim3(782, 1, 9), 128>>>(
        x, rw1, root1, p_xw1, (size_t)NN * 32, p_z, 8, nullptr, nullptr, nullptr, NN, 32);
    rgcn1_agg<<<12500, 256>>>(rb1);
    gemm2_k<32, 32, 16, 256, 8, 4, 4, 32, 0, false, false><<<dim3(391, 1, 9), 128>>>(
        p_z, rw2, root2, p_xw2, (size_t)NN * 16, p_z2r, 8, nullptr, nullptr, nullptr, NN, 16);
    rgcn2_agg<<<12500, 256>>>(rb2);

    final_kernel<<<32, 256>>>(dense_w, dense_b, out);
}

// round 15
// speedup vs baseline: 1.0473x; 1.0473x over previous
#include <cuda_runtime.h>
#include <cstdint>
#include <cstddef>
#include <math_constants.h>

#define NN 100000
#define EE 1600000
#define FIN 64
#define RR 8
#define GG 256
#define HH 4
#define CC 32
#define HC 128

// ---------------- scratch (device globals; no allocation allowed) -------------
__device__ float d_h[NN * HC];          // GAT pre-activation features
__device__ float d_asrc[NN * HH];
__device__ float d_adst[NN * HH];
__device__ int   d_deg[NN];
__device__ int   d_rowstart[NN + 1];
__device__ int   d_cursor[NN];
__device__ int   d_bsums[256];
__device__ int   d_epk[EE];             // per-(dst-sorted) edge: src | (et<<24)
__device__ float d_gat1[NN * HC];
__device__ float d_gat2[NN * 16];
__device__ float d_gmax[GG * 16];
__device__ float d_xw1[RR * NN * 32];
__device__ float d_z[NN * 32];
__device__ float d_xw2[RR * NN * 16];
__device__ float d_z2r[NN * 16];
__device__ float d_gmean[GG * 16];

// ---------------- utility ----------------
__device__ __forceinline__ float lrelu(float v, float s) { return v > 0.f ? v : s * v; }

__device__ __forceinline__ unsigned long long pk2(float lo, float hi) {
    unsigned long long r;
    asm("mov.b64 %0, {%1, %2};" : "=l"(r) : "f"(lo), "f"(hi));
    return r;
}
__device__ __forceinline__ void upk2(unsigned long long v, float& lo, float& hi) {
    asm("mov.b64 {%0, %1}, %2;" : "=f"(lo), "=f"(hi) : "l"(v));
}
__device__ __forceinline__ unsigned long long ffma2(unsigned long long a, unsigned long long b,
                                                    unsigned long long c) {
    unsigned long long d;
    asm("fma.rn.f32x2 %0, %1, %2, %3;" : "=l"(d) : "l"(a), "l"(b), "l"(c));
    return d;
}

// ---------------- zero init ----------------
__global__ void zero_kernel() {
    int i = blockIdx.x * blockDim.x + threadIdx.x;
    if (i < NN) { d_deg[i] = 0; d_cursor[i] = 0; }
    if (i < GG * 16) d_gmean[i] = 0.f;
}

// ---------------- packed-f32 tiled SGEMM  Y[r,c] = sum_k X[r,k] W[k,c] --------
// Row-pair accumulation in f32x2 registers (pack-on-the-fly W, R9 inner loop).
// sX row stride (BR+2) MUST stay even: x-pairs are read via 64-bit LDS.
// grid.z selects relation matrix (z < nRel -> Wrel/Yrel, else Wroot/Yroot).
// ACT: 0 none, 1 leaky_relu(0.01), 2 relu. FATT: fused GAT attention epilogue.
template<int K, int KC, int NCT, int BR, int TR, int TC, int TX, int TY,
         int ACT, bool BIAS, bool FATT>
__global__ __launch_bounds__(TX * TY) void gemm2_k(
    const float* __restrict__ X,
    const float* __restrict__ Wrel, const float* __restrict__ Wroot,
    float* __restrict__ Yrel, size_t yStride, float* __restrict__ Yroot,
    int nRel, const float* __restrict__ bias,
    const float* __restrict__ attS, const float* __restrict__ attD,
    int nrows, int ncolsTotal)
{
    constexpr int NT = TX * TY;
    static_assert(TY * TR == BR, "row tiling");
    static_assert(TX * TC == NCT, "col tiling");
    static_assert(TR % 2 == 0 && TC % 2 == 0, "even tiles");
    static_assert(!FATT || (TC == 8 && TX == 8 && NCT == 64), "FATT layout");

    __shared__ __align__(16) float sW[K * NCT];
    __shared__ __align__(16) float sX[KC][BR + 2];

    int z = blockIdx.z;
    const float* W = (z < nRel) ? (Wrel + (size_t)z * K * ncolsTotal) : Wroot;
    float*       Y = (z < nRel) ? (Yrel + (size_t)z * yStride)        : Yroot;

    int tid = threadIdx.x;
    int tx = tid % TX, ty = tid / TX;
    int r0 = blockIdx.x * BR;
    int c0 = blockIdx.y * NCT;

    for (int i = tid; i < K * NCT; i += NT) {
        int k = i / NCT, c = i % NCT;
        sW[i] = W[(size_t)k * ncolsTotal + c0 + c];
    }

    unsigned long long acc[TR / 2][TC];
#pragma unroll
    for (int p = 0; p < TR / 2; p++)
#pragma unroll
        for (int j = 0; j < TC; j++) acc[p][j] = 0ull;

    for (int k0 = 0; k0 < K; k0 += KC) {
        __syncthreads();
        for (int i = tid; i < BR * KC; i += NT) {
            int r = i / KC, kk = i % KC;
            float v = (r0 + r < nrows) ? X[(size_t)(r0 + r) * K + k0 + kk] : 0.f;
            sX[kk][r] = v;
        }
        __syncthreads();
#pragma unroll 8
        for (int kk = 0; kk < KC; kk++) {
            unsigned long long xp[TR / 2];
#pragma unroll
            for (int p = 0; p < TR / 2; p++)
                xp[p] = *(const unsigned long long*)&sX[kk][ty * TR + 2 * p];
            unsigned long long wp[TC];
#pragma unroll
            for (int j2 = 0; j2 < TC / 2; j2++) {
                float2 wv = *(const float2*)&sW[(k0 + kk) * NCT + tx * TC + 2 * j2];
                wp[2 * j2]     = pk2(wv.x, wv.x);
                wp[2 * j2 + 1] = pk2(wv.y, wv.y);
            }
#pragma unroll
            for (int p = 0; p < TR / 2; p++)
#pragma unroll
                for (int j = 0; j < TC; j++)
                    acc[p][j] = ffma2(xp[p], wp[j], acc[p][j]);
        }
    }

    // attention vectors (FATT only)
    float attSr[TC], attDr[TC];
    int head = 0;
    if (FATT) {
        head = blockIdx.y * 2 + (tx >> 2);
        int cb = (tx & 3) * TC;
#pragma unroll
        for (int j = 0; j < TC; j++) {
            attSr[j] = attS[head * 32 + cb + j];
            attDr[j] = attD[head * 32 + cb + j];
        }
    }

#pragma unroll
    for (int p = 0; p < TR / 2; p++) {
        float v2[2][TC];
#pragma unroll
        for (int j = 0; j < TC; j++) upk2(acc[p][j], v2[0][j], v2[1][j]);
#pragma unroll
        for (int half = 0; half < 2; half++) {
            int r = r0 + ty * TR + 2 * p + half;
            float* v = v2[half];
            if (r < nrows) {
                float o[TC];
#pragma unroll
                for (int j = 0; j < TC; j++) {
                    float t = v[j];
                    if (BIAS) t += bias[c0 + tx * TC + j];
                    if (ACT == 1) t = lrelu(t, 0.01f);
                    if (ACT == 2) t = t > 0.f ? t : 0.f;
                    o[j] = t;
                }
#pragma unroll
                for (int j4 = 0; j4 < TC; j4 += 4) {
                    float4 st = make_float4(o[j4], o[j4 + 1], o[j4 + 2], o[j4 + 3]);
                    *(float4*)&Y[(size_t)r * ncolsTotal + c0 + tx * TC + j4] = st;
                }
            }
            if (FATT) {
                float ss = 0.f, sd = 0.f;
#pragma unroll
                for (int j = 0; j < TC; j++) { ss = fmaf(v[j], attSr[j], ss); sd = fmaf(v[j], attDr[j], sd); }
                ss += __shfl_xor_sync(0xffffffffu, ss, 1);
                ss += __shfl_xor_sync(0xffffffffu, ss, 2);
                sd += __shfl_xor_sync(0xffffffffu, sd, 1);
                sd += __shfl_xor_sync(0xffffffffu, sd, 2);
                if ((tx & 3) == 0 && r < nrows) {
                    d_asrc[r * 4 + head] = ss;
                    d_adst[r * 4 + head] = sd;
                }
            }
        }
    }
}

// ---------------- CSR build ----------------
__global__ void deg_kernel(const int* __restrict__ ei) {
    int i = blockIdx.x * blockDim.x + threadIdx.x;
    if (i < EE) atomicAdd(&d_deg[ei[EE + i]], 1);
}

__global__ void scan_block() {
    __shared__ int s[1024];
    int i = blockIdx.x * 1024 + threadIdx.x;
    int v = (i < NN) ? d_deg[i] : 0;
    s[threadIdx.x] = v;
    __syncthreads();
    for (int off = 1; off < 1024; off <<= 1) {
        int t = (threadIdx.x >= off) ? s[threadIdx.x - off] : 0;
        __syncthreads();
        s[threadIdx.x] += t;
        __syncthreads();
    }
    if (i < NN) d_rowstart[i] = s[threadIdx.x] - v;   // exclusive
    if (threadIdx.x == 1023) d_bsums[blockIdx.x] = s[1023];
}

// fused: each block computes the prefix of raw block sums itself, then adds
__global__ void scan_add() {
    __shared__ int base;
    int b = blockIdx.x;
    int tid = threadIdx.x;
    if (tid < 32) {
        int acc = 0;
        for (int i = tid; i < b; i += 32) acc += d_bsums[i];
#pragma unroll
        for (int o = 16; o >= 1; o >>= 1) acc += __shfl_xor_sync(0xffffffffu, acc, o);
        if (tid == 0) base = acc;
    }
    __syncthreads();
    int i = b * 1024 + tid;
    if (i < NN) d_rowstart[i] += base;
    if (i == 0) d_rowstart[NN] = EE;
}

__global__ void scatter_kernel(const int* __restrict__ ei, const int* __restrict__ et) {
    int i = blockIdx.x * blockDim.x + threadIdx.x;
    if (i >= EE) return;
    int d = ei[EE + i];
    int pos = d_rowstart[d] + atomicAdd(&d_cursor[d], 1);
    d_epk[pos] = ei[i] | (et[i] << 24);
}

// ---------------- GAT aggregation (warp per dst node, single-pass softmax) ----
__global__ void gat_agg(const float* __restrict__ bias) {
    int w = threadIdx.x >> 5;
    int n = blockIdx.x * 8 + w;
    if (n >= NN) return;
    int lane = threadIdx.x & 31;
    int s0 = d_rowstart[n], s1 = d_rowstart[n + 1];
    int head = lane >> 3;

    float4 adAll = ((const float4*)d_adst)[n];

    __shared__ int   ssrc[8][32];
    __shared__ float sp[8][4][32];
    const float4* asrc4 = (const float4*)d_asrc;
    const float4* h4    = (const float4*)d_h;

    float4 acc = make_float4(0.f, 0.f, 0.f, 0.f);
    float ps = 0.f;

    for (int base = s0; base < s1; base += 32) {
        int cnt = min(32, s1 - base);
        if (lane < cnt) {
            int src = d_epk[base + lane] & 0xFFFFFF;
            ssrc[w][lane] = src;
            float4 as = asrc4[src];
            sp[w][0][lane] = __expf(lrelu(as.x + adAll.x, 0.2f));
            sp[w][1][lane] = __expf(lrelu(as.y + adAll.y, 0.2f));
            sp[w][2][lane] = __expf(lrelu(as.z + adAll.z, 0.2f));
            sp[w][3][lane] = __expf(lrelu(as.w + adAll.w, 0.2f));
        }
        __syncwarp();
#pragma unroll 4
        for (int j = 0; j < cnt; j++) {
            float p = sp[w][head][j];
            int src = ssrc[w][j];
            float4 hv = h4[(size_t)src * 32 + lane];
            acc.x = fmaf(p, hv.x, acc.x);
            acc.y = fmaf(p, hv.y, acc.y);
            acc.z = fmaf(p, hv.z, acc.z);
            acc.w = fmaf(p, hv.w, acc.w);
            ps += p;
        }
        __syncwarp();
    }

    float inv = (s1 > s0) ? (1.f / ps) : 0.f;
    float4 b4 = ((const float4*)bias)[lane];
    float4 o;
    o.x = lrelu(acc.x * inv + b4.x, 0.01f);
    o.y = lrelu(acc.y * inv + b4.y, 0.01f);
    o.z = lrelu(acc.z * inv + b4.z, 0.01f);
    o.w = lrelu(acc.w * inv + b4.w, 0.01f);
    ((float4*)d_gat1)[(size_t)n * 32 + lane] = o;
}

// ---------------- per-graph max pool of d_gat2 -> d_gmax ----------------
__global__ void gmax_kernel() {
    int g = blockIdx.x;
    int st = (g * NN + GG - 1) / GG;
    int en = ((g + 1) * NN + GG - 1) / GG;
    int tid = threadIdx.x;
    int col = tid % 16, part = tid / 16;            // 8 partitions
    float m = -CUDART_INF_F;
    for (int r = st + part; r < en; r += 8) m = fmaxf(m, d_gat2[(size_t)r * 16 + col]);
    __shared__ float sm[128];
    sm[tid] = m;
    __syncthreads();
    for (int o = 64; o >= 16; o >>= 1) {
        if (tid < o) sm[tid] = fmaxf(sm[tid], sm[tid + o]);
        __syncthreads();
    }
    if (tid < 16) d_gmax[g * 16 + tid] = sm[tid];
}

// ---------------- RGCN layer 1 aggregation (warp per node) ----------------
__global__ void rgcn1_agg(const float* __restrict__ rb) {
    int w = threadIdx.x >> 5;
    int n = blockIdx.x * 8 + w;
    if (n >= NN) return;
    int lane = threadIdx.x & 31;
    int s0 = d_rowstart[n], s1 = d_rowstart[n + 1];

    __shared__ int   scnt[8][8];
    __shared__ float sinv[8][8];
    __shared__ int   soff[8][32];
    __shared__ float sif[8][32];

    if (lane < 8) scnt[w][lane] = 0;
    __syncwarp();
    for (int e = s0 + lane; e < s1; e += 32) atomicAdd(&scnt[w][d_epk[e] >> 24], 1);
    __syncwarp();
    if (lane < 8) { int c = scnt[w][lane]; sinv[w][lane] = (c > 0) ? 1.f / (float)c : 0.f; }
    __syncwarp();

    float acc = 0.f;
    for (int base = s0; base < s1; base += 32) {
        int cnt = min(32, s1 - base);
        if (lane < cnt) {
            int v = d_epk[base + lane];
            int et = v >> 24, src = v & 0xFFFFFF;
            soff[w][lane] = (et * NN + src) * 32;
            sif[w][lane] = sinv[w][et];
        }
        __syncwarp();
#pragma unroll 4
        for (int j = 0; j < cnt; j++)
            acc = fmaf(__ldg(&d_xw1[soff[w][j] + lane]), sif[w][j], acc);
        __syncwarp();
    }
    float v = acc + d_z[(size_t)n * 32 + lane] + rb[lane];
    d_z[(size_t)n * 32 + lane] = v > 0.f ? v : 0.f;
}

// ---------------- RGCN layer 2 aggregation + graph-mean accumulation ----------------
__global__ void rgcn2_agg(const float* __restrict__ rb) {
    int w = threadIdx.x >> 5;
    int n = blockIdx.x * 8 + w;
    if (n >= NN) return;
    int lane = threadIdx.x & 31;
    int ch = lane & 15, par = lane >> 4;
    int s0 = d_rowstart[n], s1 = d_rowstart[n + 1];

    __shared__ int   scnt[8][8];
    __shared__ float sinv[8][8];
    __shared__ int   soff[8][32];
    __shared__ float sif[8][32];

    if (lane < 8) scnt[w][lane] = 0;
    __syncwarp();
    for (int e = s0 + lane; e < s1; e += 32) atomicAdd(&scnt[w][d_epk[e] >> 24], 1);
    __syncwarp();
    if (lane < 8) { int c = scnt[w][lane]; sinv[w][lane] = (c > 0) ? 1.f / (float)c : 0.f; }
    __syncwarp();

    float acc = 0.f;
    for (int base = s0; base < s1; base += 32) {
        int cnt = min(32, s1 - base);
        if (lane < cnt) {
            int v = d_epk[base + lane];
            int et = v >> 24, src = v & 0xFFFFFF;
            soff[w][lane] = (et * NN + src) * 16;
            sif[w][lane] = sinv[w][et];
        }
        __syncwarp();
#pragma unroll 4
        for (int j = par; j < cnt; j += 2)
            acc = fmaf(__ldg(&d_xw2[soff[w][j] + ch]), sif[w][j], acc);
        __syncwarp();
    }
    acc += __shfl_xor_sync(0xffffffffu, acc, 16);
    if (lane < 16) {
        float v = acc + d_z2r[(size_t)n * 16 + lane] + rb[lane];
        v = v > 0.f ? v : 0.f;
        int g = (n * GG) / NN;
        atomicAdd(&d_gmean[g * 16 + lane], v);
    }
}

// ---------------- final: [gmax | gmean] @ dense_w + dense_b ----------------
__global__ void final_kernel(const float* __restrict__ dw, const float* __restrict__ db,
                             float* __restrict__ out) {
    int g = blockIdx.x * 8 + (threadIdx.x >> 5);
    if (g >= GG) return;
    int lane = threadIdx.x & 31;
    int st = (g * NN + GG - 1) / GG;
    int en = ((g + 1) * NN + GG - 1) / GG;
    float npg = (float)(en - st);
    float v;
    if (lane < 16) v = d_gmax[g * 16 + lane] * dw[lane];
    else           v = (d_gmean[g * 16 + (lane - 16)] / npg) * dw[lane];
#pragma unroll
    for (int o = 16; o >= 1; o >>= 1) v += __shfl_xor_sync(0xffffffffu, v, o);
    if (lane == 0) out[g] = v + db[0];
}

// ---------------- host launcher (GAT gemm at slot 4 for ncu) ------------------
extern "C" void kernel_launch(void* const* d_in, const int* in_sizes, int n_in,
                              void* d_out, int out_size) {
    const float* x        = (const float*)d_in[0];
    const int*   ei       = (const int*)d_in[1];
    const int*   etyp     = (const int*)d_in[2];
    const float* gat_w    = (const float*)d_in[4];
    const float* att_src  = (const float*)d_in[5];
    const float* att_dst  = (const float*)d_in[6];
    const float* gat_bias = (const float*)d_in[7];
    const float* dense1_w = (const float*)d_in[8];
    const float* dense1_b = (const float*)d_in[9];
    const float* rw1      = (const float*)d_in[10];
    const float* root1    = (const float*)d_in[11];
    const float* rb1      = (const float*)d_in[12];
    const float* rw2      = (const float*)d_in[13];
    const float* root2    = (const float*)d_in[14];
    const float* rb2      = (const float*)d_in[15];
    const float* dense_w  = (const float*)d_in[16];
    const float* dense_b  = (const float*)d_in[17];
    float* out = (float*)d_out;

    float *p_h, *p_gat1, *p_gat2, *p_xw1, *p_z, *p_xw2, *p_z2r;
    cudaGetSymbolAddress((void**)&p_h, d_h);
    cudaGetSymbolAddress((void**)&p_gat1, d_gat1);
    cudaGetSymbolAddress((void**)&p_gat2, d_gat2);
    cudaGetSymbolAddress((void**)&p_xw1, d_xw1);
    cudaGetSymbolAddress((void**)&p_z, d_z);
    cudaGetSymbolAddress((void**)&p_xw2, d_xw2);
    cudaGetSymbolAddress((void**)&p_z2r, d_z2r);

    // 1-3
    zero_kernel<<<(NN + 255) / 256, 256>>>();
    deg_kernel<<<6250, 256>>>(ei);
    scan_block<<<98, 1024>>>();
    // 4: GAT feature GEMM (+ fused attention scalars), slimmer TR=4 tile — profiled
    gemm2_k<64, 32, 64, 128, 4, 8, 8, 32, 0, false, true><<<dim3(782, 2, 1), 256>>>(
        x, nullptr, gat_w, nullptr, 0, p_h, 0, nullptr, att_src, att_dst, NN, HC);
    // 5-6: rest of CSR build
    scan_add<<<98, 1024>>>();
    scatter_kernel<<<6250, 256>>>(ei, etyp);

    // GAT branch
    gat_agg<<<12500, 256>>>(gat_bias);
    gemm2_k<128, 32, 16, 256, 8, 4, 4, 32, 1, true, false><<<dim3(391, 1, 1), 128>>>(
        p_gat1, nullptr, dense1_w, nullptr, 0, p_gat2, 0, dense1_b, nullptr, nullptr, NN, 16);
    gmax_kernel<<<GG, 128>>>();

    // RGCN branch
    gemm2_k<64, 32, 32, 128, 8, 4, 8, 16, 0, false, false><<<dim3(782, 1, 9), 128>>>(
        x, rw1, root1, p_xw1, (size_t)NN * 32, p_z, 8, nullptr, nullptr, nullptr, NN, 32);
    rgcn1_agg<<<12500, 256>>>(rb1);
    gemm2_k<32, 32, 16, 256, 8, 4, 4, 32, 0, false, false><<<dim3(391, 1, 9), 128>>>(
        p_z, rw2, root2, p_xw2, (size_t)NN * 16, p_z2r, 8, nullptr, nullptr, nullptr, NN, 16);
    rgcn2_agg<<<12500, 256>>>(rb2);

    final_kernel<<<32, 256>>>(dense_w, dense_b, out);
}

// round 16
// speedup vs baseline: 1.0957x; 1.0462x over previous
#include <cuda_runtime.h>
#include <cuda_bf16.h>
#include <cstdint>
#include <cstddef>
#include <math_constants.h>

#define NN 100000
#define EE 1600000
#define FIN 64
#define RR 8
#define GG 256
#define HH 4
#define CC 32
#define HC 128

// ---------------- scratch (device globals; no allocation allowed) -------------
__device__ float d_h[NN * HC];          // GAT pre-activation features
__device__ float d_asrc[NN * HH];
__device__ float d_adst[NN * HH];
__device__ int   d_deg[NN];
__device__ int   d_rowstart[NN + 1];
__device__ int   d_cursor[NN];
__device__ int   d_bsums[256];
__device__ int   d_epk[EE];             // per-(dst-sorted) edge: src | (et<<24)
__device__ float d_gat1[NN * HC];
__device__ float d_gat2[NN * 16];
__device__ float d_gmax[GG * 16];
__device__ __nv_bfloat16 d_xw1b[RR * NN * 32];   // bf16 per-relation transforms
__device__ float d_z[NN * 32];
__device__ __nv_bfloat16 d_xw2b[RR * NN * 16];
__device__ float d_z2r[NN * 16];
__device__ float d_gmean[GG * 16];

// ---------------- utility ----------------
__device__ __forceinline__ float lrelu(float v, float s) { return v > 0.f ? v : s * v; }

__device__ __forceinline__ unsigned long long pk2(float lo, float hi) {
    unsigned long long r;
    asm("mov.b64 %0, {%1, %2};" : "=l"(r) : "f"(lo), "f"(hi));
    return r;
}
__device__ __forceinline__ void upk2(unsigned long long v, float& lo, float& hi) {
    asm("mov.b64 {%0, %1}, %2;" : "=f"(lo), "=f"(hi) : "l"(v));
}
__device__ __forceinline__ unsigned long long ffma2(unsigned long long a, unsigned long long b,
                                                    unsigned long long c) {
    unsigned long long d;
    asm("fma.rn.f32x2 %0, %1, %2, %3;" : "=l"(d) : "l"(a), "l"(b), "l"(c));
    return d;
}

// ---------------- zero init ----------------
__global__ void zero_kernel() {
    int i = blockIdx.x * blockDim.x + threadIdx.x;
    if (i < NN) { d_deg[i] = 0; d_cursor[i] = 0; }
    if (i < GG * 16) d_gmean[i] = 0.f;
}

// ---------------- packed-f32 tiled SGEMM  Y[r,c] = sum_k X[r,k] W[k,c] --------
// Row-pair accumulation in f32x2 registers (pack-on-the-fly W, R9 inner loop).
// sX row stride (BR+2) MUST stay even: x-pairs are read via 64-bit LDS.
// grid.z selects relation matrix (z < nRel -> Wrel/Yrel, else Wroot/Yroot).
// OUTBF: per-relation outputs stored as bf16 (root output stays fp32).
// ACT: 0 none, 1 leaky_relu(0.01), 2 relu. FATT: fused GAT attention epilogue.
template<int K, int KC, int NCT, int BR, int TR, int TC, int TX, int TY,
         int ACT, bool BIAS, bool FATT, bool OUTBF>
__global__ __launch_bounds__(TX * TY) void gemm2_k(
    const float* __restrict__ X,
    const float* __restrict__ Wrel, const float* __restrict__ Wroot,
    float* __restrict__ Yrel, __nv_bfloat16* __restrict__ YrelB,
    size_t yStride, float* __restrict__ Yroot,
    int nRel, const float* __restrict__ bias,
    const float* __restrict__ attS, const float* __restrict__ attD,
    int nrows, int ncolsTotal)
{
    constexpr int NT = TX * TY;
    static_assert(TY * TR == BR, "row tiling");
    static_assert(TX * TC == NCT, "col tiling");
    static_assert(TR % 2 == 0 && TC % 2 == 0, "even tiles");
    static_assert(!OUTBF || TC % 4 == 0, "bf16 path stores uint2");
    static_assert(!FATT || (TC == 8 && TX == 8 && NCT == 64), "FATT layout");

    __shared__ __align__(16) float sW[K * NCT];
    __shared__ __align__(16) float sX[KC][BR + 2];

    int z = blockIdx.z;
    const float* W = (z < nRel) ? (Wrel + (size_t)z * K * ncolsTotal) : Wroot;

    int tid = threadIdx.x;
    int tx = tid % TX, ty = tid / TX;
    int r0 = blockIdx.x * BR;
    int c0 = blockIdx.y * NCT;

    for (int i = tid; i < K * NCT; i += NT) {
        int k = i / NCT, c = i % NCT;
        sW[i] = W[(size_t)k * ncolsTotal + c0 + c];
    }

    unsigned long long acc[TR / 2][TC];
#pragma unroll
    for (int p = 0; p < TR / 2; p++)
#pragma unroll
        for (int j = 0; j < TC; j++) acc[p][j] = 0ull;

    for (int k0 = 0; k0 < K; k0 += KC) {
        __syncthreads();
        for (int i = tid; i < BR * KC; i += NT) {
            int r = i / KC, kk = i % KC;
            float v = (r0 + r < nrows) ? X[(size_t)(r0 + r) * K + k0 + kk] : 0.f;
            sX[kk][r] = v;
        }
        __syncthreads();
#pragma unroll 8
        for (int kk = 0; kk < KC; kk++) {
            unsigned long long xp[TR / 2];
#pragma unroll
            for (int p = 0; p < TR / 2; p++)
                xp[p] = *(const unsigned long long*)&sX[kk][ty * TR + 2 * p];
            unsigned long long wp[TC];
#pragma unroll
            for (int j2 = 0; j2 < TC / 2; j2++) {
                float2 wv = *(const float2*)&sW[(k0 + kk) * NCT + tx * TC + 2 * j2];
                wp[2 * j2]     = pk2(wv.x, wv.x);
                wp[2 * j2 + 1] = pk2(wv.y, wv.y);
            }
#pragma unroll
            for (int p = 0; p < TR / 2; p++)
#pragma unroll
                for (int j = 0; j < TC; j++)
                    acc[p][j] = ffma2(xp[p], wp[j], acc[p][j]);
        }
    }

    // attention vectors (FATT only)
    float attSr[TC], attDr[TC];
    int head = 0;
    if (FATT) {
        head = blockIdx.y * 2 + (tx >> 2);
        int cb = (tx & 3) * TC;
#pragma unroll
        for (int j = 0; j < TC; j++) {
            attSr[j] = attS[head * 32 + cb + j];
            attDr[j] = attD[head * 32 + cb + j];
        }
    }

#pragma unroll
    for (int p = 0; p < TR / 2; p++) {
        float v2[2][TC];
#pragma unroll
        for (int j = 0; j < TC; j++) upk2(acc[p][j], v2[0][j], v2[1][j]);
#pragma unroll
        for (int half = 0; half < 2; half++) {
            int r = r0 + ty * TR + 2 * p + half;
            float* v = v2[half];
            if (r < nrows) {
                float o[TC];
#pragma unroll
                for (int j = 0; j < TC; j++) {
                    float t = v[j];
                    if (BIAS) t += bias[c0 + tx * TC + j];
                    if (ACT == 1) t = lrelu(t, 0.01f);
                    if (ACT == 2) t = t > 0.f ? t : 0.f;
                    o[j] = t;
                }
                if (OUTBF && z < nRel) {
                    __nv_bfloat16* Yb = YrelB + (size_t)z * yStride;
#pragma unroll
                    for (int j4 = 0; j4 < TC; j4 += 4) {
                        __nv_bfloat162 b0 = __float22bfloat162_rn(make_float2(o[j4], o[j4 + 1]));
                        __nv_bfloat162 b1 = __float22bfloat162_rn(make_float2(o[j4 + 2], o[j4 + 3]));
                        uint2 st2;
                        st2.x = *(unsigned*)&b0;
                        st2.y = *(unsigned*)&b1;
                        *(uint2*)&Yb[(size_t)r * ncolsTotal + c0 + tx * TC + j4] = st2;
                    }
                } else {
                    float* Y = (z < nRel) ? (Yrel + (size_t)z * yStride) : Yroot;
#pragma unroll
                    for (int j4 = 0; j4 < TC; j4 += 4) {
                        float4 st = make_float4(o[j4], o[j4 + 1], o[j4 + 2], o[j4 + 3]);
                        *(float4*)&Y[(size_t)r * ncolsTotal + c0 + tx * TC + j4] = st;
                    }
                }
            }
            if (FATT) {
                float ss = 0.f, sd = 0.f;
#pragma unroll
                for (int j = 0; j < TC; j++) { ss = fmaf(v[j], attSr[j], ss); sd = fmaf(v[j], attDr[j], sd); }
                ss += __shfl_xor_sync(0xffffffffu, ss, 1);
                ss += __shfl_xor_sync(0xffffffffu, ss, 2);
                sd += __shfl_xor_sync(0xffffffffu, sd, 1);
                sd += __shfl_xor_sync(0xffffffffu, sd, 2);
                if ((tx & 3) == 0 && r < nrows) {
                    d_asrc[r * 4 + head] = ss;
                    d_adst[r * 4 + head] = sd;
                }
            }
        }
    }
}

// ---------------- CSR build ----------------
__global__ void deg_kernel(const int* __restrict__ ei) {
    int i = blockIdx.x * blockDim.x + threadIdx.x;
    if (i < EE) atomicAdd(&d_deg[ei[EE + i]], 1);
}

__global__ void scan_block() {
    __shared__ int s[1024];
    int i = blockIdx.x * 1024 + threadIdx.x;
    int v = (i < NN) ? d_deg[i] : 0;
    s[threadIdx.x] = v;
    __syncthreads();
    for (int off = 1; off < 1024; off <<= 1) {
        int t = (threadIdx.x >= off) ? s[threadIdx.x - off] : 0;
        __syncthreads();
        s[threadIdx.x] += t;
        __syncthreads();
    }
    if (i < NN) d_rowstart[i] = s[threadIdx.x] - v;   // exclusive
    if (threadIdx.x == 1023) d_bsums[blockIdx.x] = s[1023];
}

// fused: each block computes the prefix of raw block sums itself, then adds
__global__ void scan_add() {
    __shared__ int base;
    int b = blockIdx.x;
    int tid = threadIdx.x;
    if (tid < 32) {
        int acc = 0;
        for (int i = tid; i < b; i += 32) acc += d_bsums[i];
#pragma unroll
        for (int o = 16; o >= 1; o >>= 1) acc += __shfl_xor_sync(0xffffffffu, acc, o);
        if (tid == 0) base = acc;
    }
    __syncthreads();
    int i = b * 1024 + tid;
    if (i < NN) d_rowstart[i] += base;
    if (i == 0) d_rowstart[NN] = EE;
}

__global__ void scatter_kernel(const int* __restrict__ ei, const int* __restrict__ et) {
    int i = blockIdx.x * blockDim.x + threadIdx.x;
    if (i >= EE) return;
    int d = ei[EE + i];
    int pos = d_rowstart[d] + atomicAdd(&d_cursor[d], 1);
    d_epk[pos] = ei[i] | (et[i] << 24);
}

// ---------------- GAT aggregation (warp per dst node, single-pass softmax) ----
__global__ void gat_agg(const float* __restrict__ bias) {
    int w = threadIdx.x >> 5;
    int n = blockIdx.x * 8 + w;
    if (n >= NN) return;
    int lane = threadIdx.x & 31;
    int s0 = d_rowstart[n], s1 = d_rowstart[n + 1];
    int head = lane >> 3;

    float4 adAll = ((const float4*)d_adst)[n];

    __shared__ int   ssrc[8][32];
    __shared__ float sp[8][4][32];
    const float4* asrc4 = (const float4*)d_asrc;
    const float4* h4    = (const float4*)d_h;

    float4 acc = make_float4(0.f, 0.f, 0.f, 0.f);
    float ps = 0.f;

    for (int base = s0; base < s1; base += 32) {
        int cnt = min(32, s1 - base);
        if (lane < cnt) {
            int src = d_epk[base + lane] & 0xFFFFFF;
            ssrc[w][lane] = src;
            float4 as = asrc4[src];
            sp[w][0][lane] = __expf(lrelu(as.x + adAll.x, 0.2f));
            sp[w][1][lane] = __expf(lrelu(as.y + adAll.y, 0.2f));
            sp[w][2][lane] = __expf(lrelu(as.z + adAll.z, 0.2f));
            sp[w][3][lane] = __expf(lrelu(as.w + adAll.w, 0.2f));
        }
        __syncwarp();
#pragma unroll 4
        for (int j = 0; j < cnt; j++) {
            float p = sp[w][head][j];
            int src = ssrc[w][j];
            float4 hv = h4[(size_t)src * 32 + lane];
            acc.x = fmaf(p, hv.x, acc.x);
            acc.y = fmaf(p, hv.y, acc.y);
            acc.z = fmaf(p, hv.z, acc.z);
            acc.w = fmaf(p, hv.w, acc.w);
            ps += p;
        }
        __syncwarp();
    }

    float inv = (s1 > s0) ? (1.f / ps) : 0.f;
    float4 b4 = ((const float4*)bias)[lane];
    float4 o;
    o.x = lrelu(acc.x * inv + b4.x, 0.01f);
    o.y = lrelu(acc.y * inv + b4.y, 0.01f);
    o.z = lrelu(acc.z * inv + b4.z, 0.01f);
    o.w = lrelu(acc.w * inv + b4.w, 0.01f);
    ((float4*)d_gat1)[(size_t)n * 32 + lane] = o;
}

// ---------------- per-graph max pool of d_gat2 -> d_gmax ----------------
__global__ void gmax_kernel() {
    int g = blockIdx.x;
    int st = (g * NN + GG - 1) / GG;
    int en = ((g + 1) * NN + GG - 1) / GG;
    int tid = threadIdx.x;
    int col = tid % 16, part = tid / 16;            // 8 partitions
    float m = -CUDART_INF_F;
    for (int r = st + part; r < en; r += 8) m = fmaxf(m, d_gat2[(size_t)r * 16 + col]);
    __shared__ float sm[128];
    sm[tid] = m;
    __syncthreads();
    for (int o = 64; o >= 16; o >>= 1) {
        if (tid < o) sm[tid] = fmaxf(sm[tid], sm[tid + o]);
        __syncthreads();
    }
    if (tid < 16) d_gmax[g * 16 + tid] = sm[tid];
}

// ---------------- RGCN layer 1 aggregation (warp per node, bf16 gather) -------
__global__ void rgcn1_agg(const float* __restrict__ rb) {
    int w = threadIdx.x >> 5;
    int n = blockIdx.x * 8 + w;
    if (n >= NN) return;
    int lane = threadIdx.x & 31;
    int s0 = d_rowstart[n], s1 = d_rowstart[n + 1];

    __shared__ int   scnt[8][8];
    __shared__ float sinv[8][8];
    __shared__ int   soff[8][32];
    __shared__ float sif[8][32];

    if (lane < 8) scnt[w][lane] = 0;
    __syncwarp();
    for (int e = s0 + lane; e < s1; e += 32) atomicAdd(&scnt[w][d_epk[e] >> 24], 1);
    __syncwarp();
    if (lane < 8) { int c = scnt[w][lane]; sinv[w][lane] = (c > 0) ? 1.f / (float)c : 0.f; }
    __syncwarp();

    float acc = 0.f;
    for (int base = s0; base < s1; base += 32) {
        int cnt = min(32, s1 - base);
        if (lane < cnt) {
            int v = d_epk[base + lane];
            int et = v >> 24, src = v & 0xFFFFFF;
            soff[w][lane] = (et * NN + src) * 32;
            sif[w][lane] = sinv[w][et];
        }
        __syncwarp();
#pragma unroll 4
        for (int j = 0; j < cnt; j++)
            acc = fmaf(__bfloat162float(__ldg(&d_xw1b[soff[w][j] + lane])), sif[w][j], acc);
        __syncwarp();
    }
    float v = acc + d_z[(size_t)n * 32 + lane] + rb[lane];
    d_z[(size_t)n * 32 + lane] = v > 0.f ? v : 0.f;
}

// ---------------- RGCN layer 2 aggregation + graph-mean (bf16 gather) ---------
__global__ void rgcn2_agg(const float* __restrict__ rb) {
    int w = threadIdx.x >> 5;
    int n = blockIdx.x * 8 + w;
    if (n >= NN) return;
    int lane = threadIdx.x & 31;
    int ch = lane & 15, par = lane >> 4;
    int s0 = d_rowstart[n], s1 = d_rowstart[n + 1];

    __shared__ int   scnt[8][8];
    __shared__ float sinv[8][8];
    __shared__ int   soff[8][32];
    __shared__ float sif[8][32];

    if (lane < 8) scnt[w][lane] = 0;
    __syncwarp();
    for (int e = s0 + lane; e < s1; e += 32) atomicAdd(&scnt[w][d_epk[e] >> 24], 1);
    __syncwarp();
    if (lane < 8) { int c = scnt[w][lane]; sinv[w][lane] = (c > 0) ? 1.f / (float)c : 0.f; }
    __syncwarp();

    float acc = 0.f;
    for (int base = s0; base < s1; base += 32) {
        int cnt = min(32, s1 - base);
        if (lane < cnt) {
            int v = d_epk[base + lane];
            int et = v >> 24, src = v & 0xFFFFFF;
            soff[w][lane] = (et * NN + src) * 16;
            sif[w][lane] = sinv[w][et];
        }
        __syncwarp();
#pragma unroll 4
        for (int j = par; j < cnt; j += 2)
            acc = fmaf(__bfloat162float(__ldg(&d_xw2b[soff[w][j] + ch])), sif[w][j], acc);
        __syncwarp();
    }
    acc += __shfl_xor_sync(0xffffffffu, acc, 16);
    if (lane < 16) {
        float v = acc + d_z2r[(size_t)n * 16 + lane] + rb[lane];
        v = v > 0.f ? v : 0.f;
        int g = (n * GG) / NN;
        atomicAdd(&d_gmean[g * 16 + lane], v);
    }
}

// ---------------- final: [gmax | gmean] @ dense_w + dense_b ----------------
__global__ void final_kernel(const float* __restrict__ dw, const float* __restrict__ db,
                             float* __restrict__ out) {
    int g = blockIdx.x * 8 + (threadIdx.x >> 5);
    if (g >= GG) return;
    int lane = threadIdx.x & 31;
    int st = (g * NN + GG - 1) / GG;
    int en = ((g + 1) * NN + GG - 1) / GG;
    float npg = (float)(en - st);
    float v;
    if (lane < 16) v = d_gmax[g * 16 + lane] * dw[lane];
    else           v = (d_gmean[g * 16 + (lane - 16)] / npg) * dw[lane];
#pragma unroll
    for (int o = 16; o >= 1; o >>= 1) v += __shfl_xor_sync(0xffffffffu, v, o);
    if (lane == 0) out[g] = v + db[0];
}

// ---------------- host launcher (R9 ordering; xw1 GEMM at slot 4) -------------
extern "C" void kernel_launch(void* const* d_in, const int* in_sizes, int n_in,
                              void* d_out, int out_size) {
    const float* x        = (const float*)d_in[0];
    const int*   ei       = (const int*)d_in[1];
    const int*   etyp     = (const int*)d_in[2];
    const float* gat_w    = (const float*)d_in[4];
    const float* att_src  = (const float*)d_in[5];
    const float* att_dst  = (const float*)d_in[6];
    const float* gat_bias = (const float*)d_in[7];
    const float* dense1_w = (const float*)d_in[8];
    const float* dense1_b = (const float*)d_in[9];
    const float* rw1      = (const float*)d_in[10];
    const float* root1    = (const float*)d_in[11];
    const float* rb1      = (const float*)d_in[12];
    const float* rw2      = (const float*)d_in[13];
    const float* root2    = (const float*)d_in[14];
    const float* rb2      = (const float*)d_in[15];
    const float* dense_w  = (const float*)d_in[16];
    const float* dense_b  = (const float*)d_in[17];
    float* out = (float*)d_out;

    float *p_h, *p_gat1, *p_gat2, *p_z, *p_z2r;
    __nv_bfloat16 *p_xw1b, *p_xw2b;
    cudaGetSymbolAddress((void**)&p_h, d_h);
    cudaGetSymbolAddress((void**)&p_gat1, d_gat1);
    cudaGetSymbolAddress((void**)&p_gat2, d_gat2);
    cudaGetSymbolAddress((void**)&p_xw1b, d_xw1b);
    cudaGetSymbolAddress((void**)&p_z, d_z);
    cudaGetSymbolAddress((void**)&p_xw2b, d_xw2b);
    cudaGetSymbolAddress((void**)&p_z2r, d_z2r);

    // 1
    zero_kernel<<<(NN + 255) / 256, 256>>>();
    // 2: GAT feature GEMM (+ fused attention scalars)
    gemm2_k<64, 32, 64, 128, 8, 8, 8, 16, 0, false, true, false><<<dim3(782, 2, 1), 128>>>(
        x, nullptr, gat_w, nullptr, nullptr, 0, p_h, 0, nullptr, att_src, att_dst, NN, HC);
    // 3
    deg_kernel<<<6250, 256>>>(ei);
    // 4: RGCN layer-1 GEMMs (bf16 rel outputs) — profiled slot
    gemm2_k<64, 32, 32, 128, 8, 4, 8, 16, 0, false, false, true><<<dim3(782, 1, 9), 128>>>(
        x, rw1, root1, nullptr, p_xw1b, (size_t)NN * 32, p_z, 8, nullptr, nullptr, nullptr, NN, 32);
    // 5-7: rest of CSR build
    scan_block<<<98, 1024>>>();
    scan_add<<<98, 1024>>>();
    scatter_kernel<<<6250, 256>>>(ei, etyp);

    // GAT branch
    gat_agg<<<12500, 256>>>(gat_bias);
    gemm2_k<128, 32, 16, 256, 8, 4, 4, 32, 1, true, false, false><<<dim3(391, 1, 1), 128>>>(
        p_gat1, nullptr, dense1_w, nullptr, nullptr, 0, p_gat2, 0, dense1_b, nullptr, nullptr, NN, 16);
    gmax_kernel<<<GG, 128>>>();

    // RGCN branch
    rgcn1_agg<<<12500, 256>>>(rb1);
    gemm2_k<32, 32, 16, 256, 8, 4, 4, 32, 0, false, false, true><<<dim3(391, 1, 9), 128>>>(
        p_z, rw2, root2, nullptr, p_xw2b, (size_t)NN * 16, p_z2r, 8, nullptr, nullptr, nullptr, NN, 16);
    rgcn2_agg<<<12500, 256>>>(rb2);

    final_kernel<<<32, 256>>>(dense_w, dense_b, out);
}